// round 2
// baseline (speedup 1.0000x reference)
#include <cuda_runtime.h>

#define B_   1024
#define G_   512
#define K_   128
#define J_   129
#define E2_  128
#define KJ_  16512   // K_ * J_

// ---------------- device scratch (no allocations allowed) ----------------
__device__ float d_wnorm1[K_];        // ||wimg[:,k]||^2
__device__ float d_wrecnorm[K_];      // ||wrec[k,:]||^2
__device__ float d_wrec2norm[J_];     // ||wrec2[j,:]||^2
__device__ float d_q[K_ * J_];        // sum_g wimg2[g,k,j]^2
__device__ float d_xpd[B_ * K_];      // xp_d (= xp after step 3)
__device__ int   d_idx[B_];
__device__ float d_xp2d[B_ * J_];
__device__ float d_partial[B_ * 8];   // per (b, g-block) loss partials

// ---------------- norms ----------------
__global__ void k_norms(const float* __restrict__ wimg,
                        const float* __restrict__ wrec,
                        const float* __restrict__ wrec2) {
    int t = threadIdx.x;
    if (t < K_) {
        float s = 0.f;
        for (int g = 0; g < G_; ++g) { float v = wimg[g * K_ + t]; s += v * v; }
        d_wnorm1[t] = s;
    }
    if (t < K_) {
        float s = 0.f; const float* r = wrec + t * E2_;
        for (int e = 0; e < E2_; ++e) s += r[e] * r[e];
        d_wrecnorm[t] = s;
    }
    if (t < J_) {
        float s = 0.f; const float* r = wrec2 + t * E2_;
        for (int e = 0; e < E2_; ++e) s += r[e] * r[e];
        d_wrec2norm[t] = s;
    }
}

__global__ void k_q(const float* __restrict__ wimg2) {
    int t = blockIdx.x * 256 + threadIdx.x;
    if (t >= KJ_) return;
    float s = 0.f;
    for (int g = 0; g < G_; ++g) {
        float v = wimg2[(size_t)g * KJ_ + t];
        s += v * v;
    }
    d_q[t] = s;
}

// ---------------- encode stage 1: xp1 -> lat -> xp_d, idx ----------------
// grid = B_, block = 128, dyn smem = SMEM_B
__global__ void k_encode1(const float* __restrict__ images,
                          const float* __restrict__ wimg,
                          const float* __restrict__ wrec) {
    extern __shared__ float sm[];
    float* wrec_s = sm;                 // 128 rows, stride 129 -> 16512 floats
    float* img_s  = wrec_s + 16512;     // 512
    float* xp1_s  = img_s + 512;        // 128
    float* lat_s  = xp1_s + 128;        // 128
    float* redv   = lat_s + 128;        // 128
    int*   redi   = (int*)(redv + 128); // 128

    int b = blockIdx.x, t = threadIdx.x;

    for (int i = t; i < K_ * E2_; i += 128)
        wrec_s[(i >> 7) * 129 + (i & 127)] = wrec[i];
    for (int i = t; i < G_; i += 128)
        img_s[i] = images[b * G_ + i];
    __syncthreads();

    // logits1: (2 * images[b]·wimg[:,t] - ||wimg[:,t]||^2) / G
    float dot = 0.f;
#pragma unroll 4
    for (int g = 0; g < G_; ++g) dot += img_s[g] * wimg[g * K_ + t];
    float lg = (2.f * dot - d_wnorm1[t]) * (1.f / 512.f);

    // softmax over 128
    redv[t] = lg; __syncthreads();
    for (int s = 64; s; s >>= 1) { if (t < s) redv[t] = fmaxf(redv[t], redv[t + s]); __syncthreads(); }
    float mx = redv[0]; __syncthreads();
    float ev = __expf(lg - mx);
    redv[t] = ev; __syncthreads();
    for (int s = 64; s; s >>= 1) { if (t < s) redv[t] += redv[t + s]; __syncthreads(); }
    float xp1 = ev / redv[0];
    __syncthreads();
    xp1_s[t] = xp1; __syncthreads();

    // lat[e] = sum_k xp1[k] * wrec[k,e]
    float l = 0.f;
#pragma unroll 4
    for (int k = 0; k < K_; ++k) l += xp1_s[k] * wrec_s[k * 129 + t];
    lat_s[t] = l; __syncthreads();

    // xp_d logits: (2 * lat·wrec[t,:] - ||wrec[t,:]||^2) / E2
    float d2 = 0.f;
#pragma unroll 4
    for (int e = 0; e < E2_; ++e) d2 += lat_s[e] * wrec_s[t * 129 + e];
    float lg2 = (2.f * d2 - d_wrecnorm[t]) * (1.f / 128.f);

    // argmax (first occurrence on ties) + max value
    redv[t] = lg2; redi[t] = t; __syncthreads();
    for (int s = 64; s; s >>= 1) {
        if (t < s) {
            float ov = redv[t + s]; int oi = redi[t + s];
            if (ov > redv[t] || (ov == redv[t] && oi < redi[t])) { redv[t] = ov; redi[t] = oi; }
        }
        __syncthreads();
    }
    if (t == 0) d_idx[b] = redi[0];
    float mx2 = redv[0];
    __syncthreads();

    float ev2 = __expf(lg2 - mx2);
    redv[t] = ev2; __syncthreads();
    for (int s = 64; s; s >>= 1) { if (t < s) redv[t] += redv[t + s]; __syncthreads(); }
    d_xpd[b * K_ + t] = ev2 / redv[0];
}

// ---------------- encode stage 2 + decode assignment: xp2 -> lat2 -> xp2_d ----------------
// grid = B_, block = 256, dyn smem = SMEM_C
__global__ void k_encode2(const float* __restrict__ images,
                          const float* __restrict__ wimg,
                          const float* __restrict__ wrec2,
                          const float* __restrict__ wimg2) {
    extern __shared__ float sm[];
    float* wrec2_s = sm;                // 129 rows, stride 129 -> 16641
    float* r_s     = wrec2_s + 16641;   // 512
    float* xp2_s   = r_s + 512;         // 132
    float* lat2_s  = xp2_s + 132;       // 128
    float* redv    = lat2_s + 128;      // 256

    int b = blockIdx.x, t = threadIdx.x;
    int idx = d_idx[b];

    for (int i = t; i < J_ * E2_; i += 256)
        wrec2_s[(i >> 7) * 129 + (i & 127)] = wrec2[i];
    for (int g = t; g < G_; g += 256)
        r_s[g] = images[b * G_ + g] - wimg[g * K_ + idx];
    __syncthreads();

    // logits2[j] = (2 * sum_g r[g]*wimg2[g,idx,j] - q[idx,j]) / G
    float lg = -INFINITY;
    if (t < J_) {
        const float* w2 = wimg2 + (size_t)idx * J_ + t;
        float s0 = 0.f, s1 = 0.f, s2 = 0.f, s3 = 0.f;
        for (int g = 0; g < G_; g += 4) {
            s0 += r_s[g]     * w2[(size_t)g * KJ_];
            s1 += r_s[g + 1] * w2[(size_t)(g + 1) * KJ_];
            s2 += r_s[g + 2] * w2[(size_t)(g + 2) * KJ_];
            s3 += r_s[g + 3] * w2[(size_t)(g + 3) * KJ_];
        }
        float dotj = (s0 + s1) + (s2 + s3);
        lg = (2.f * dotj - d_q[idx * J_ + t]) * (1.f / 512.f);
    }
    // softmax over 129 (inactive threads contribute -inf / 0)
    redv[t] = lg; __syncthreads();
    for (int s = 128; s; s >>= 1) { if (t < s) redv[t] = fmaxf(redv[t], redv[t + s]); __syncthreads(); }
    float mx = redv[0]; __syncthreads();
    float ev = (t < J_) ? __expf(lg - mx) : 0.f;
    redv[t] = ev; __syncthreads();
    for (int s = 128; s; s >>= 1) { if (t < s) redv[t] += redv[t + s]; __syncthreads(); }
    float inv = 1.f / redv[0];
    __syncthreads();
    if (t < J_) xp2_s[t] = ev * inv;
    __syncthreads();

    // lat2[e] = sum_j xp2[j] * wrec2[j,e]
    if (t < E2_) {
        float l = 0.f;
#pragma unroll 4
        for (int j = 0; j < J_; ++j) l += xp2_s[j] * wrec2_s[j * 129 + t];
        lat2_s[t] = l;
    }
    __syncthreads();

    // xp2_d logits: (2 * lat2·wrec2[t,:] - ||wrec2[t,:]||^2) / E2
    float lg2 = -INFINITY;
    if (t < J_) {
        float d = 0.f;
#pragma unroll 4
        for (int e = 0; e < E2_; ++e) d += lat2_s[e] * wrec2_s[t * 129 + e];
        lg2 = (2.f * d - d_wrec2norm[t]) * (1.f / 128.f);
    }
    redv[t] = lg2; __syncthreads();
    for (int s = 128; s; s >>= 1) { if (t < s) redv[t] = fmaxf(redv[t], redv[t + s]); __syncthreads(); }
    float mx2 = redv[0]; __syncthreads();
    float ev2 = (t < J_) ? __expf(lg2 - mx2) : 0.f;
    redv[t] = ev2; __syncthreads();
    for (int s = 128; s; s >>= 1) { if (t < s) redv[t] += redv[t + s]; __syncthreads(); }
    float inv2 = 1.f / redv[0];
    if (t < J_) d_xp2d[b * J_ + t] = ev2 * inv2;
}

// ---------------- main GEMM: xrec = P @ W^T (+ wimg term) and loss partials ----------------
// C[b,g] = sum_{k,j} xp[b,k]*xp2d[b,j]*wimg2[g,k,j] + sum_k xp[b,k]*wimg[g,k]
// grid = (G_/64, B_/64) = (8, 16), block = 256, dyn smem = SMEM_D
__global__ void k_gemm(const float* __restrict__ images,
                       const float* __restrict__ wimg,
                       const float* __restrict__ wimg2) {
    extern __shared__ float sm[];
    float* xp_s  = sm;              // 64 rows stride 129 -> 8256
    float* xp2_s = xp_s + 8256;     // 8256
    float* P_s   = xp2_s + 8256;    // [t][b] 32*64 = 2048
    float* W_s   = P_s + 2048;      // [t][g] stride 65 -> 2080

    int tid = threadIdx.x;
    int g0 = blockIdx.x * 64, b0 = blockIdx.y * 64;

    for (int i = tid; i < 64 * 128; i += 256) {
        int b = i >> 7, k = i & 127;
        xp_s[b * 129 + k] = d_xpd[(b0 + b) * K_ + k];
    }
    for (int i = tid; i < 64 * 129; i += 256) {
        int b = i / 129, j = i - b * 129;
        xp2_s[b * 129 + j] = d_xp2d[(b0 + b) * J_ + j];
    }

    float acc[4][4];
#pragma unroll
    for (int a = 0; a < 4; ++a)
#pragma unroll
        for (int c = 0; c < 4; ++c) acc[a][c] = 0.f;

    int tx = tid & 15, ty = tid >> 4;
    int gb = tx * 4, bb = ty * 4;
    int bP = tid & 63, tB = tid >> 6;    // P fill: fixed b, 8 t's
    int tgW = tid & 31, gW = tid >> 5;   // W fill: fixed tg, 8 g's

    const float* w2g = wimg2 + (size_t)g0 * KJ_;

    for (int c = 0; c < 520; ++c) {
        __syncthreads();   // also orders initial xp_s/xp2_s loads before first fill
        if (c < 516) {
            int kj0 = c * 32;
#pragma unroll
            for (int p = 0; p < 8; ++p) {
                int t = tB + p * 4;
                unsigned kj = (unsigned)(kj0 + t);
                unsigned k = kj / 129u;
                unsigned j = kj - k * 129u;
                P_s[t * 64 + bP] = xp_s[bP * 129 + k] * xp2_s[bP * 129 + j];
            }
#pragma unroll
            for (int p = 0; p < 8; ++p) {
                int g = gW + p * 8;
                W_s[tgW * 65 + g] = w2g[(size_t)g * KJ_ + kj0 + tgW];
            }
        } else {
            int k0 = (c - 516) * 32;
#pragma unroll
            for (int p = 0; p < 8; ++p) {
                int t = tB + p * 4;
                P_s[t * 64 + bP] = xp_s[bP * 129 + k0 + t];
            }
#pragma unroll
            for (int p = 0; p < 8; ++p) {
                int g = gW + p * 8;
                W_s[tgW * 65 + g] = wimg[(g0 + g) * K_ + k0 + tgW];
            }
        }
        __syncthreads();
#pragma unroll 8
        for (int t = 0; t < 32; ++t) {
            float4 pv = *(const float4*)&P_s[t * 64 + bb];
            float w0 = W_s[t * 65 + gb + 0];
            float w1 = W_s[t * 65 + gb + 1];
            float w2 = W_s[t * 65 + gb + 2];
            float w3 = W_s[t * 65 + gb + 3];
            acc[0][0] += pv.x * w0; acc[0][1] += pv.x * w1; acc[0][2] += pv.x * w2; acc[0][3] += pv.x * w3;
            acc[1][0] += pv.y * w0; acc[1][1] += pv.y * w1; acc[1][2] += pv.y * w2; acc[1][3] += pv.y * w3;
            acc[2][0] += pv.z * w0; acc[2][1] += pv.z * w1; acc[2][2] += pv.z * w2; acc[2][3] += pv.z * w3;
            acc[3][0] += pv.w * w0; acc[3][1] += pv.w * w1; acc[3][2] += pv.w * w2; acc[3][3] += pv.w * w3;
        }
    }
    __syncthreads();

    // loss partials: sum over this g-tile of (xrec - images)^2 per b
    float part[4];
#pragma unroll
    for (int bi = 0; bi < 4; ++bi) {
        const float4 im = *(const float4*)&images[(size_t)(b0 + bb + bi) * G_ + g0 + gb];
        float e0 = acc[bi][0] - im.x, e1 = acc[bi][1] - im.y;
        float e2 = acc[bi][2] - im.z, e3 = acc[bi][3] - im.w;
        part[bi] = e0 * e0 + e1 * e1 + e2 * e2 + e3 * e3;
    }
    float* red = P_s;   // reuse 2048-float buffer as [64][16]
#pragma unroll
    for (int bi = 0; bi < 4; ++bi) red[(bb + bi) * 16 + tx] = part[bi];
    __syncthreads();
    if (tid < 64) {
        float s = 0.f;
#pragma unroll
        for (int q = 0; q < 16; ++q) s += red[tid * 16 + q];
        d_partial[(size_t)(b0 + tid) * 8 + blockIdx.x] = s;
    }
}

// ---------------- final deterministic reduce ----------------
__global__ void k_reduce(float* __restrict__ out) {
    int b = blockIdx.x * 256 + threadIdx.x;
    if (b < B_) {
        float s = 0.f;
#pragma unroll
        for (int q = 0; q < 8; ++q) s += d_partial[b * 8 + q];
        out[b] = s * (1.f / 512.f);
    }
}

// ---------------- launch ----------------
extern "C" void kernel_launch(void* const* d_in, const int* in_sizes, int n_in,
                              void* d_out, int out_size) {
    const float* images = (const float*)d_in[0];
    const float* wimg   = (const float*)d_in[1];
    const float* wrec   = (const float*)d_in[2];
    const float* wrec2  = (const float*)d_in[3];
    const float* wimg2  = (const float*)d_in[4];
    float* out = (float*)d_out;

    const int SMEM_B = (16512 + 512 + 128 + 128 + 128 + 128) * 4;   // 70144
    const int SMEM_C = (16641 + 512 + 132 + 128 + 256) * 4;         // 70676
    const int SMEM_D = (8256 + 8256 + 2048 + 2080) * 4;             // 82560

    cudaFuncSetAttribute(k_encode1, cudaFuncAttributeMaxDynamicSharedMemorySize, SMEM_B);
    cudaFuncSetAttribute(k_encode2, cudaFuncAttributeMaxDynamicSharedMemorySize, SMEM_C);
    cudaFuncSetAttribute(k_gemm,    cudaFuncAttributeMaxDynamicSharedMemorySize, SMEM_D);

    k_norms<<<1, 256>>>(wimg, wrec, wrec2);
    k_q<<<(KJ_ + 255) / 256, 256>>>(wimg2);
    k_encode1<<<B_, 128, SMEM_B>>>(images, wimg, wrec);
    k_encode2<<<B_, 256, SMEM_C>>>(images, wimg, wrec2, wimg2);
    k_gemm<<<dim3(8, 16), 256, SMEM_D>>>(images, wimg, wimg2);
    k_reduce<<<4, 256>>>(out);
}

// round 4
// speedup vs baseline: 2.7762x; 2.7762x over previous
#include <cuda_runtime.h>
#include <cstdint>

#define B_   1024
#define G_   512
#define K_   128
#define J_   129
#define E2_  128
#define KJ_  16512   // K_ * J_
#define KE_  16640   // KJ_ + K_ (wimg folded in as extra K)
#define NSPLIT_ 4
#define NCHTOT_ 520  // 16640 / 32
#define NCH_ 130     // chunks per split
#define GSTAGES 3
#define STAGE_B 32768
#define SMEM_G (GSTAGES * STAGE_B)

// ---------------- device scratch (no allocations allowed) ----------------
__device__ float d_wnorm1[K_];
__device__ float d_wrecnorm[K_];
__device__ float d_wrec2norm[J_];
__device__ float d_q[K_ * J_];
__device__ float d_xpd[B_ * K_];
__device__ int   d_idx[B_];
__device__ float d_xp2d[B_ * J_];
__device__ float d_P[(size_t)B_ * KE_];        // 68 MB
__device__ float d_c2[NSPLIT_][B_][G_];        // split-K partials

// ---------------- helpers ----------------
__device__ __forceinline__ uint32_t s2u(const void* p) {
    uint32_t r;
    asm("{ .reg .u64 t; cvta.to.shared.u64 t, %1; cvt.u32.u64 %0, t; }" : "=r"(r) : "l"(p));
    return r;
}
__device__ __forceinline__ void cp16(uint32_t dst, const void* src) {
    asm volatile("cp.async.cg.shared.global [%0], [%1], 16;" :: "r"(dst), "l"(src) : "memory");
}
#define SWZ(o) ((o) ^ ((((unsigned)(o)) >> 3) & 0x70u))

__device__ __forceinline__ void mma_tf32(float* c, const uint32_t* a, const uint32_t* b) {
    asm volatile(
        "mma.sync.aligned.m16n8k8.row.col.f32.tf32.tf32.f32 "
        "{%0,%1,%2,%3}, {%4,%5,%6,%7}, {%8,%9}, {%0,%1,%2,%3};"
        : "+f"(c[0]), "+f"(c[1]), "+f"(c[2]), "+f"(c[3])
        : "r"(a[0]), "r"(a[1]), "r"(a[2]), "r"(a[3]), "r"(b[0]), "r"(b[1]));
}

// ---------------- norms ----------------
__global__ void k_norms(const float* __restrict__ wimg,
                        const float* __restrict__ wrec,
                        const float* __restrict__ wrec2) {
    int t = threadIdx.x;
    if (t < K_) {
        float s = 0.f;
        for (int g = 0; g < G_; ++g) { float v = wimg[g * K_ + t]; s += v * v; }
        d_wnorm1[t] = s;
    }
    if (t < K_) {
        float s = 0.f; const float* r = wrec + t * E2_;
        for (int e = 0; e < E2_; ++e) s += r[e] * r[e];
        d_wrecnorm[t] = s;
    }
    if (t < J_) {
        float s = 0.f; const float* r = wrec2 + t * E2_;
        for (int e = 0; e < E2_; ++e) s += r[e] * r[e];
        d_wrec2norm[t] = s;
    }
}

__global__ void k_q(const float* __restrict__ wimg2) {
    int t = blockIdx.x * 256 + threadIdx.x;
    if (t >= KJ_) return;
    float s = 0.f;
    for (int g = 0; g < G_; ++g) {
        float v = wimg2[(size_t)g * KJ_ + t];
        s += v * v;
    }
    d_q[t] = s;
}

// ---------------- encode stage 1 ----------------
__global__ void k_encode1(const float* __restrict__ images,
                          const float* __restrict__ wimg,
                          const float* __restrict__ wrec) {
    extern __shared__ float sm[];
    float* wrec_s = sm;
    float* img_s  = wrec_s + 16512;
    float* xp1_s  = img_s + 512;
    float* lat_s  = xp1_s + 128;
    float* redv   = lat_s + 128;
    int*   redi   = (int*)(redv + 128);

    int b = blockIdx.x, t = threadIdx.x;

    for (int i = t; i < K_ * E2_; i += 128)
        wrec_s[(i >> 7) * 129 + (i & 127)] = wrec[i];
    for (int i = t; i < G_; i += 128)
        img_s[i] = images[b * G_ + i];
    __syncthreads();

    float dot = 0.f;
#pragma unroll 4
    for (int g = 0; g < G_; ++g) dot += img_s[g] * wimg[g * K_ + t];
    float lg = (2.f * dot - d_wnorm1[t]) * (1.f / 512.f);

    redv[t] = lg; __syncthreads();
    for (int s = 64; s; s >>= 1) { if (t < s) redv[t] = fmaxf(redv[t], redv[t + s]); __syncthreads(); }
    float mx = redv[0]; __syncthreads();
    float ev = __expf(lg - mx);
    redv[t] = ev; __syncthreads();
    for (int s = 64; s; s >>= 1) { if (t < s) redv[t] += redv[t + s]; __syncthreads(); }
    float xp1 = ev / redv[0];
    __syncthreads();
    xp1_s[t] = xp1; __syncthreads();

    float l = 0.f;
#pragma unroll 4
    for (int k = 0; k < K_; ++k) l += xp1_s[k] * wrec_s[k * 129 + t];
    lat_s[t] = l; __syncthreads();

    float d2 = 0.f;
#pragma unroll 4
    for (int e = 0; e < E2_; ++e) d2 += lat_s[e] * wrec_s[t * 129 + e];
    float lg2 = (2.f * d2 - d_wrecnorm[t]) * (1.f / 128.f);

    redv[t] = lg2; redi[t] = t; __syncthreads();
    for (int s = 64; s; s >>= 1) {
        if (t < s) {
            float ov = redv[t + s]; int oi = redi[t + s];
            if (ov > redv[t] || (ov == redv[t] && oi < redi[t])) { redv[t] = ov; redi[t] = oi; }
        }
        __syncthreads();
    }
    if (t == 0) d_idx[b] = redi[0];
    float mx2 = redv[0];
    __syncthreads();

    float ev2 = __expf(lg2 - mx2);
    redv[t] = ev2; __syncthreads();
    for (int s = 64; s; s >>= 1) { if (t < s) redv[t] += redv[t + s]; __syncthreads(); }
    d_xpd[b * K_ + t] = ev2 / redv[0];
}

// ---------------- encode stage 2 ----------------
__global__ void k_encode2(const float* __restrict__ images,
                          const float* __restrict__ wimg,
                          const float* __restrict__ wrec2,
                          const float* __restrict__ wimg2) {
    extern __shared__ float sm[];
    float* wrec2_s = sm;
    float* r_s     = wrec2_s + 16641;
    float* xp2_s   = r_s + 512;
    float* lat2_s  = xp2_s + 132;
    float* redv    = lat2_s + 128;

    int b = blockIdx.x, t = threadIdx.x;
    int idx = d_idx[b];

    for (int i = t; i < J_ * E2_; i += 256)
        wrec2_s[(i >> 7) * 129 + (i & 127)] = wrec2[i];
    for (int g = t; g < G_; g += 256)
        r_s[g] = images[b * G_ + g] - wimg[g * K_ + idx];
    __syncthreads();

    float lg = -INFINITY;
    if (t < J_) {
        const float* w2 = wimg2 + (size_t)idx * J_ + t;
        float s0 = 0.f, s1 = 0.f, s2 = 0.f, s3 = 0.f;
        for (int g = 0; g < G_; g += 4) {
            s0 += r_s[g]     * w2[(size_t)g * KJ_];
            s1 += r_s[g + 1] * w2[(size_t)(g + 1) * KJ_];
            s2 += r_s[g + 2] * w2[(size_t)(g + 2) * KJ_];
            s3 += r_s[g + 3] * w2[(size_t)(g + 3) * KJ_];
        }
        float dotj = (s0 + s1) + (s2 + s3);
        lg = (2.f * dotj - d_q[idx * J_ + t]) * (1.f / 512.f);
    }
    redv[t] = lg; __syncthreads();
    for (int s = 128; s; s >>= 1) { if (t < s) redv[t] = fmaxf(redv[t], redv[t + s]); __syncthreads(); }
    float mx = redv[0]; __syncthreads();
    float ev = (t < J_) ? __expf(lg - mx) : 0.f;
    redv[t] = ev; __syncthreads();
    for (int s = 128; s; s >>= 1) { if (t < s) redv[t] += redv[t + s]; __syncthreads(); }
    float inv = 1.f / redv[0];
    __syncthreads();
    if (t < J_) xp2_s[t] = ev * inv;
    __syncthreads();

    if (t < E2_) {
        float l = 0.f;
#pragma unroll 4
        for (int j = 0; j < J_; ++j) l += xp2_s[j] * wrec2_s[j * 129 + t];
        lat2_s[t] = l;
    }
    __syncthreads();

    float lg2 = -INFINITY;
    if (t < J_) {
        float d = 0.f;
#pragma unroll 4
        for (int e = 0; e < E2_; ++e) d += lat2_s[e] * wrec2_s[t * 129 + e];
        lg2 = (2.f * d - d_wrec2norm[t]) * (1.f / 128.f);
    }
    redv[t] = lg2; __syncthreads();
    for (int s = 128; s; s >>= 1) { if (t < s) redv[t] = fmaxf(redv[t], redv[t + s]); __syncthreads(); }
    float mx2 = redv[0]; __syncthreads();
    float ev2 = (t < J_) ? __expf(lg2 - mx2) : 0.f;
    redv[t] = ev2; __syncthreads();
    for (int s = 128; s; s >>= 1) { if (t < s) redv[t] += redv[t + s]; __syncthreads(); }
    float inv2 = 1.f / redv[0];
    if (t < J_) d_xp2d[b * J_ + t] = ev2 * inv2;
}

// ---------------- build P ----------------
__global__ void k_buildP() {
    __shared__ float xp_s[128];
    __shared__ float xp2_s[129];
    int b = blockIdx.x, t = threadIdx.x;
    if (t < 128) xp_s[t] = d_xpd[b * K_ + t];
    if (t < 129) xp2_s[t] = d_xp2d[b * J_ + t];
    __syncthreads();
    float* dst = d_P + (size_t)b * KE_;
    for (int i = t; i < KE_; i += 256) {
        float v;
        if (i < KJ_) {
            unsigned k = (unsigned)i / 129u;
            unsigned j = (unsigned)i - k * 129u;
            v = xp_s[k] * xp2_s[j];
        } else {
            v = xp_s[i - KJ_];
        }
        dst[i] = v;
    }
}

// ---------------- tf32 mma.sync GEMM ----------------
// grid (4, 8, 4) = (g-tile, b-tile, k-split), 256 threads
// CTA tile 128(b) x 128(g), BK=32, warp tile 64x32, m16n8k8 tf32
__global__ __launch_bounds__(256, 1)
void k_tgemm(const float* __restrict__ wimg,
             const float* __restrict__ wimg2) {
    extern __shared__ char smem[];
    uint32_t sb = s2u(smem);
    int tid = threadIdx.x;
    int lane = tid & 31, wid = tid >> 5;
    int wm = wid >> 2, wn = wid & 3;        // warp grid 2(m) x 4(n)
    int row_l = lane >> 2, kq = lane & 3;
    unsigned axorm = (unsigned)row_l << 4;  // SW128 xor mask (row%8 invariant)

    int g0 = blockIdx.x * 128, b0 = blockIdx.y * 128, ks = blockIdx.z;
    int cbase = ks * NCH_;
    const float* pbase = d_P + (size_t)b0 * KE_;

    // stage fill: A = P[128b x 32k], B = W[128g x 32k], SW128 swizzled
    auto fill = [&](int cl, int s) {
        int c = cbase + cl;
        uint32_t abase = sb + s * STAGE_B;
        uint32_t bbase = abase + 16384;
        const char* psrc = (const char*)(pbase + (size_t)c * 32);
        const char* wsrc;
        size_t wstr;
        if (c < 516) { wsrc = (const char*)(wimg2 + (size_t)g0 * KJ_ + (size_t)c * 32); wstr = (size_t)KJ_ * 4; }
        else         { wsrc = (const char*)(wimg + (size_t)g0 * K_ + (size_t)(c - 516) * 32); wstr = (size_t)K_ * 4; }
#pragma unroll
        for (int p = 0; p < 4; ++p) {
            int i = tid + p * 256;
            int row = i >> 3;
            int cb = (i & 7) << 4;
            uint32_t sw = SWZ(row * 128 + cb);
            cp16(abase + sw, psrc + (size_t)row * (KE_ * 4) + cb);
            cp16(bbase + sw, wsrc + (size_t)row * wstr + cb);
        }
    };

    float acc[4][4][4];
#pragma unroll
    for (int mt = 0; mt < 4; ++mt)
#pragma unroll
        for (int nt = 0; nt < 4; ++nt)
#pragma unroll
            for (int q = 0; q < 4; ++q) acc[mt][nt][q] = 0.f;

    // prologue: fill stages 0..GSTAGES-2
#pragma unroll
    for (int cl = 0; cl < GSTAGES - 1; ++cl) {
        fill(cl, cl);
        asm volatile("cp.async.commit_group;" ::: "memory");
    }

    for (int it = 0; it < NCH_; ++it) {
        asm volatile("cp.async.wait_group %0;" :: "n"(GSTAGES - 2) : "memory");
        __syncthreads();

        int cf = it + GSTAGES - 1;
        if (cf < NCH_) fill(cf, cf % GSTAGES);
        asm volatile("cp.async.commit_group;" ::: "memory");

        const char* As = smem + (it % GSTAGES) * STAGE_B;
        const char* Bs = As + 16384;

#pragma unroll
        for (int kst = 0; kst < 4; ++kst) {
            uint32_t af[4][4];
#pragma unroll
            for (int mt = 0; mt < 4; ++mt) {
                unsigned m = wm * 64 + mt * 16 + row_l;
                unsigned base = m * 128 + (kst * 8 + kq) * 4;
                af[mt][0] = *(const uint32_t*)(As + (base ^ axorm));
                af[mt][1] = *(const uint32_t*)(As + ((base + 8 * 128) ^ axorm));
                af[mt][2] = *(const uint32_t*)(As + ((base + 16) ^ axorm));
                af[mt][3] = *(const uint32_t*)(As + ((base + 8 * 128 + 16) ^ axorm));
            }
            uint32_t bf[4][2];
#pragma unroll
            for (int nt = 0; nt < 4; ++nt) {
                unsigned n = wn * 32 + nt * 8 + row_l;
                unsigned base = n * 128 + (kst * 8 + kq) * 4;
                bf[nt][0] = *(const uint32_t*)(Bs + (base ^ axorm));
                bf[nt][1] = *(const uint32_t*)(Bs + ((base + 16) ^ axorm));
            }
#pragma unroll
            for (int mt = 0; mt < 4; ++mt)
#pragma unroll
                for (int nt = 0; nt < 4; ++nt)
                    mma_tf32(acc[mt][nt], af[mt], bf[nt]);
        }
    }

    // epilogue: write split partials
#pragma unroll
    for (int mt = 0; mt < 4; ++mt) {
#pragma unroll
        for (int nt = 0; nt < 4; ++nt) {
            int grow = b0 + wm * 64 + mt * 16 + row_l;
            int gcol = g0 + wn * 32 + nt * 8 + kq * 2;
            *(float2*)&d_c2[ks][grow][gcol]     = make_float2(acc[mt][nt][0], acc[mt][nt][1]);
            *(float2*)&d_c2[ks][grow + 8][gcol] = make_float2(acc[mt][nt][2], acc[mt][nt][3]);
        }
    }
}

// ---------------- final loss ----------------
__global__ void k_loss(const float* __restrict__ images, float* __restrict__ out) {
    int b = blockIdx.x, t = threadIdx.x;
    float s = 0.f;
    for (int g = t; g < G_; g += 128) {
        float v = d_c2[0][b][g] + d_c2[1][b][g] + d_c2[2][b][g] + d_c2[3][b][g]
                - images[b * G_ + g];
        s += v * v;
    }
    __shared__ float red[128];
    red[t] = s; __syncthreads();
    for (int q = 64; q; q >>= 1) { if (t < q) red[t] += red[t + q]; __syncthreads(); }
    if (t == 0) out[b] = red[0] * (1.f / 512.f);
}

// ---------------- launch ----------------
extern "C" void kernel_launch(void* const* d_in, const int* in_sizes, int n_in,
                              void* d_out, int out_size) {
    const float* images = (const float*)d_in[0];
    const float* wimg   = (const float*)d_in[1];
    const float* wrec   = (const float*)d_in[2];
    const float* wrec2  = (const float*)d_in[3];
    const float* wimg2  = (const float*)d_in[4];
    float* out = (float*)d_out;

    const int SMEM_B = (16512 + 512 + 128 + 128 + 128 + 128) * 4;
    const int SMEM_C = (16641 + 512 + 132 + 128 + 256) * 4;

    cudaFuncSetAttribute(k_encode1, cudaFuncAttributeMaxDynamicSharedMemorySize, SMEM_B);
    cudaFuncSetAttribute(k_encode2, cudaFuncAttributeMaxDynamicSharedMemorySize, SMEM_C);
    cudaFuncSetAttribute(k_tgemm,   cudaFuncAttributeMaxDynamicSharedMemorySize, SMEM_G);

    k_norms<<<1, 256>>>(wimg, wrec, wrec2);
    k_q<<<(KJ_ + 255) / 256, 256>>>(wimg2);
    k_encode1<<<B_, 128, SMEM_B>>>(images, wimg, wrec);
    k_encode2<<<B_, 256, SMEM_C>>>(images, wimg, wrec2, wimg2);
    k_buildP<<<B_, 256>>>();
    k_tgemm<<<dim3(4, 8, NSPLIT_), 256, SMEM_G>>>(wimg, wimg2);
    k_loss<<<B_, 128>>>(images, out);
}

// round 5
// speedup vs baseline: 4.1169x; 1.4829x over previous
#include <cuda_runtime.h>
#include <cuda_fp16.h>
#include <cstdint>

#define B_   1024
#define G_   512
#define K_   128
#define J_   129
#define KJ_  16512   // K_ * J_
#define KE_  16640   // KJ_ + K_ (wimg folded in as extra K)
#define NSPLIT_ 4
#define NCH_ 65      // 64-wide k-chunks per split (260 total)
#define GSTAGES 3
#define STAGE_B 32768
#define SMEM_G (GSTAGES * STAGE_B)

// ---------------- device scratch (no allocations allowed) ----------------
__device__ float d_wrecnorm[K_];
__device__ float d_wrec2norm[J_];
__device__ float d_wnorm1[K_];
__device__ float d_q[KJ_];
__device__ float d_corr[KJ_];
__device__ float d_qp[8][KJ_];
__device__ float d_cp[8][KJ_];
__device__ float d_wnp[8][K_];
__device__ float d_xpd[B_ * K_];
__device__ int   d_idx[B_];
__device__ float d_xp2d[B_ * J_];
__device__ float d_dot2[B_ * J_];
__device__ __half d_Ph[(size_t)B_ * KE_];    // 34 MB
__device__ __half d_w2h[(size_t)G_ * KE_];   // 17 MB (wimg2 + wimg ext, f16)
__device__ float d_c2[NSPLIT_][B_][G_];

// ---------------- helpers ----------------
__device__ __forceinline__ uint32_t s2u(const void* p) {
    uint32_t r;
    asm("{ .reg .u64 t; cvta.to.shared.u64 t, %1; cvt.u32.u64 %0, t; }" : "=r"(r) : "l"(p));
    return r;
}
__device__ __forceinline__ void cp16(uint32_t dst, const void* src) {
    asm volatile("cp.async.cg.shared.global [%0], [%1], 16;" :: "r"(dst), "l"(src) : "memory");
}
#define SWZ(o) ((o) ^ ((((unsigned)(o)) >> 3) & 0x70u))

__device__ __forceinline__ void mma_f16(float* c, const uint32_t* a, const uint32_t* b) {
    asm volatile(
        "mma.sync.aligned.m16n8k16.row.col.f32.f16.f16.f32 "
        "{%0,%1,%2,%3}, {%4,%5,%6,%7}, {%8,%9}, {%0,%1,%2,%3};"
        : "+f"(c[0]), "+f"(c[1]), "+f"(c[2]), "+f"(c[3])
        : "r"(a[0]), "r"(a[1]), "r"(a[2]), "r"(a[3]), "r"(b[0]), "r"(b[1]));
}

// kj -> k for kj < 16512 (divide by 129): exact for this range
__device__ __forceinline__ unsigned div129(unsigned kj) {
    return (kj * 32515u) >> 22;
}

// ---------------- wimg2 pass: q, corr, wnorm1 partials + f16 conversion ----------------
// grid (65, 8), block 256
__global__ void k_prep1(const float* __restrict__ wimg,
                        const float* __restrict__ wimg2) {
    int t = blockIdx.x * 256 + threadIdx.x;   // kj in [0, 16640)
    int gh = blockIdx.y;
    int gbeg = gh * 64;
    if (t < KJ_) {
        unsigned k = div129((unsigned)t);
        float q = 0.f, c = 0.f;
        for (int gg = 0; gg < 64; ++gg) {
            int g = gbeg + gg;
            float v = wimg2[(size_t)g * KJ_ + t];
            float wi = wimg[g * K_ + k];
            q += v * v;
            c += wi * v;
            d_w2h[(size_t)g * KE_ + t] = __float2half(v);
        }
        d_qp[gh][t] = q;
        d_cp[gh][t] = c;
    } else if (t < KE_) {
        int kk = t - KJ_;
        float s = 0.f;
        for (int gg = 0; gg < 64; ++gg) {
            int g = gbeg + gg;
            float v = wimg[g * K_ + kk];
            s += v * v;
            d_w2h[(size_t)g * KE_ + t] = __float2half(v);
        }
        d_wnp[gh][kk] = s;
    }
}

// grid 65, block 256 — reduce the 8 g-partials
__global__ void k_qred() {
    int t = blockIdx.x * 256 + threadIdx.x;
    if (t < KJ_) {
        float q = 0.f, c = 0.f;
#pragma unroll
        for (int h = 0; h < 8; ++h) { q += d_qp[h][t]; c += d_cp[h][t]; }
        d_q[t] = q;
        d_corr[t] = c;
    } else if (t < KE_) {
        int kk = t - KJ_;
        float s = 0.f;
#pragma unroll
        for (int h = 0; h < 8; ++h) s += d_wnp[h][kk];
        d_wnorm1[kk] = s;
    }
}

// ---------------- small norms ----------------
__global__ void k_norms(const float* __restrict__ wrec,
                        const float* __restrict__ wrec2) {
    int t = threadIdx.x;
    if (t < K_) {
        float s = 0.f; const float* r = wrec + t * 128;
        for (int e = 0; e < 128; ++e) s += r[e] * r[e];
        d_wrecnorm[t] = s;
    }
    if (t < J_) {
        float s = 0.f; const float* r = wrec2 + t * 128;
        for (int e = 0; e < 128; ++e) s += r[e] * r[e];
        d_wrec2norm[t] = s;
    }
}

// ---------------- encode stage 1: 8 b's per block ----------------
// grid 128, block 256
#define SMEM_E1 ((16512 + 4096 + 2048 + 128 + 128 + 256) * 4 + 256 * 4)
__global__ void k_encode1(const float* __restrict__ images,
                          const float* __restrict__ wimg,
                          const float* __restrict__ wrec) {
    extern __shared__ float sm[];
    float* wrec_s = sm;             // 128 rows x stride 129 = 16512
    float* img_s  = wrec_s + 16512; // 8 x 512 = 4096
    float* dotp   = img_s + 4096;   // [2][8][128] = 2048
    float* xp1_s  = dotp + 2048;    // 128
    float* lat_s  = xp1_s + 128;    // 128
    float* redv   = lat_s + 128;    // 256
    int*   redi   = (int*)(redv + 256); // 256

    int t = threadIdx.x;
    int b0 = blockIdx.x * 8;

    for (int i = t; i < 16384; i += 256)
        wrec_s[(i >> 7) * 129 + (i & 127)] = wrec[i];
    for (int i = t; i < 4096; i += 256)
        img_s[i] = images[b0 * 512 + i];
    __syncthreads();

    // dot phase: thread (k = t&127, g-half = t>>7) accumulates 8 b's
    int k = t & 127, gh = t >> 7;
    float lg8[8];
#pragma unroll
    for (int bi = 0; bi < 8; ++bi) lg8[bi] = 0.f;
    for (int gg = 0; gg < 256; ++gg) {
        int g = gh * 256 + gg;
        float w = wimg[g * 128 + k];
#pragma unroll
        for (int bi = 0; bi < 8; ++bi) lg8[bi] += w * img_s[bi * 512 + g];
    }
#pragma unroll
    for (int bi = 0; bi < 8; ++bi) dotp[gh * 1024 + bi * 128 + k] = lg8[bi];
    __syncthreads();

    for (int bi = 0; bi < 8; ++bi) {
        int b = b0 + bi;
        float lg = 0.f;
        if (t < 128) {
            float dot = dotp[bi * 128 + t] + dotp[1024 + bi * 128 + t];
            lg = (2.f * dot - d_wnorm1[t]) * (1.f / 512.f);
        }
        // softmax over k
        redv[t] = (t < 128) ? lg : -INFINITY; __syncthreads();
        for (int s = 128; s; s >>= 1) { if (t < s) redv[t] = fmaxf(redv[t], redv[t + s]); __syncthreads(); }
        float mx = redv[0]; __syncthreads();
        float ev = (t < 128) ? __expf(lg - mx) : 0.f;
        redv[t] = ev; __syncthreads();
        for (int s = 128; s; s >>= 1) { if (t < s) redv[t] += redv[t + s]; __syncthreads(); }
        if (t < 128) xp1_s[t] = ev / redv[0];
        __syncthreads();

        // lat[e] = sum_k xp1[k] wrec[k,e]
        if (t < 128) {
            float l = 0.f;
#pragma unroll 4
            for (int kk = 0; kk < 128; ++kk) l += xp1_s[kk] * wrec_s[kk * 129 + t];
            lat_s[t] = l;
        }
        __syncthreads();

        float lg2 = 0.f;
        if (t < 128) {
            float d2 = 0.f;
#pragma unroll 4
            for (int e = 0; e < 128; ++e) d2 += lat_s[e] * wrec_s[t * 129 + e];
            lg2 = (2.f * d2 - d_wrecnorm[t]) * (1.f / 128.f);
        }
        // argmax (first occurrence) + softmax
        redv[t] = (t < 128) ? lg2 : -INFINITY;
        redi[t] = (t < 128) ? t : 9999;
        __syncthreads();
        for (int s = 128; s; s >>= 1) {
            if (t < s) {
                float ov = redv[t + s]; int oi = redi[t + s];
                if (ov > redv[t] || (ov == redv[t] && oi < redi[t])) { redv[t] = ov; redi[t] = oi; }
            }
            __syncthreads();
        }
        if (t == 0) d_idx[b] = redi[0];
        float mx2 = redv[0]; __syncthreads();
        float ev2 = (t < 128) ? __expf(lg2 - mx2) : 0.f;
        redv[t] = ev2; __syncthreads();
        for (int s = 128; s; s >>= 1) { if (t < s) redv[t] += redv[t + s]; __syncthreads(); }
        if (t < 128) d_xpd[b * 128 + t] = ev2 / redv[0];
        __syncthreads();
    }
}

// ---------------- dot2: images[b] . w2h[:, idx_b*129 + j], g-parallel coalesced ----------------
// grid 1024, block 256
__global__ void k_dot2(const float* __restrict__ images) {
    __shared__ float img_s[512];
    __shared__ float part[8][136];
    int b = blockIdx.x, t = threadIdx.x, lane = t & 31, w = t >> 5;
    for (int i = t; i < 512; i += 256) img_s[i] = images[b * 512 + i];
    __syncthreads();
    int idx = d_idx[b];
    const __half* colb = d_w2h + (size_t)idx * 129;
    float a0 = 0.f, a1 = 0.f, a2 = 0.f, a3 = 0.f, a4 = 0.f;
    for (int g = w; g < 512; g += 8) {
        float iv = img_s[g];
        const __half* rp = colb + (size_t)g * KE_;
        a0 += iv * __half2float(rp[lane]);
        a1 += iv * __half2float(rp[lane + 32]);
        a2 += iv * __half2float(rp[lane + 64]);
        a3 += iv * __half2float(rp[lane + 96]);
        if (lane == 0) a4 += iv * __half2float(rp[128]);
    }
    part[w][lane] = a0; part[w][lane + 32] = a1;
    part[w][lane + 64] = a2; part[w][lane + 96] = a3;
    if (lane == 0) part[w][128] = a4;
    __syncthreads();
    if (t < 129) {
        float s = 0.f;
#pragma unroll
        for (int ww = 0; ww < 8; ++ww) s += part[ww][t];
        d_dot2[b * J_ + t] = s;
    }
}

// ---------------- encode2 tail: softmax -> lat2 -> xp2d, 8 b's per block ----------------
// grid 128, block 256
#define SMEM_E2 ((16641 + 132 + 128 + 256) * 4)
__global__ void k_encode2b(const float* __restrict__ wrec2) {
    extern __shared__ float sm[];
    float* wrec2_s = sm;              // 129 rows x stride 129 = 16641
    float* xp2_s   = wrec2_s + 16641; // 132
    float* lat2_s  = xp2_s + 132;     // 128
    float* redv    = lat2_s + 128;    // 256

    int t = threadIdx.x;
    int b0 = blockIdx.x * 8;

    for (int i = t; i < 16512; i += 256)
        wrec2_s[(i >> 7) * 129 + (i & 127)] = wrec2[i];
    __syncthreads();

    for (int bi = 0; bi < 8; ++bi) {
        int b = b0 + bi;
        int idx = d_idx[b];
        float lg = -INFINITY;
        if (t < J_) {
            float dotr = d_dot2[b * J_ + t] - d_corr[idx * J_ + t];
            lg = (2.f * dotr - d_q[idx * J_ + t]) * (1.f / 512.f);
        }
        redv[t] = lg; __syncthreads();
        for (int s = 128; s; s >>= 1) { if (t < s) redv[t] = fmaxf(redv[t], redv[t + s]); __syncthreads(); }
        float mx = redv[0]; __syncthreads();
        float ev = (t < J_) ? __expf(lg - mx) : 0.f;
        redv[t] = ev; __syncthreads();
        for (int s = 128; s; s >>= 1) { if (t < s) redv[t] += redv[t + s]; __syncthreads(); }
        float inv = 1.f / redv[0]; __syncthreads();
        if (t < J_) xp2_s[t] = ev * inv;
        __syncthreads();

        if (t < 128) {
            float l = 0.f;
#pragma unroll 4
            for (int j = 0; j < J_; ++j) l += xp2_s[j] * wrec2_s[j * 129 + t];
            lat2_s[t] = l;
        }
        __syncthreads();

        float lg2 = -INFINITY;
        if (t < J_) {
            float d = 0.f;
#pragma unroll 4
            for (int e = 0; e < 128; ++e) d += lat2_s[e] * wrec2_s[t * 129 + e];
            lg2 = (2.f * d - d_wrec2norm[t]) * (1.f / 128.f);
        }
        redv[t] = lg2; __syncthreads();
        for (int s = 128; s; s >>= 1) { if (t < s) redv[t] = fmaxf(redv[t], redv[t + s]); __syncthreads(); }
        float mx2 = redv[0]; __syncthreads();
        float ev2 = (t < J_) ? __expf(lg2 - mx2) : 0.f;
        redv[t] = ev2; __syncthreads();
        for (int s = 128; s; s >>= 1) { if (t < s) redv[t] += redv[t + s]; __syncthreads(); }
        if (t < J_) d_xp2d[b * J_ + t] = ev2 * (1.f / redv[0]);
        __syncthreads();
    }
}

// ---------------- build P (f16) ----------------
// grid 1024, block 256
__global__ void k_buildP() {
    __shared__ float xp_s[128];
    __shared__ float xp2_s[132];
    int b = blockIdx.x, t = threadIdx.x;
    if (t < 128) xp_s[t] = d_xpd[b * 128 + t];
    if (t < 129) xp2_s[t] = d_xp2d[b * J_ + t];
    __syncthreads();
    __half2* dst = (__half2*)(d_Ph + (size_t)b * KE_);
    for (int i2 = t; i2 < KE_ / 2; i2 += 256) {
        int kj = i2 * 2;
        float v0, v1;
        if (kj < KJ_) {
            unsigned k = div129((unsigned)kj);
            unsigned j = (unsigned)kj - k * 129u;
            float xk = xp_s[k];
            v0 = xk * xp2_s[j];
            v1 = (j < 128) ? xk * xp2_s[j + 1] : xp_s[k + 1] * xp2_s[0];
        } else {
            v0 = xp_s[kj - KJ_];
            v1 = xp_s[kj - KJ_ + 1];
        }
        dst[i2] = __floats2half2_rn(v0, v1);
    }
}

// ---------------- f16 mma.sync GEMM ----------------
// grid (4, 8, 4) = (g-tile, b-tile, k-split), 256 threads
// CTA tile 128(b) x 128(g), BK=64 f16 (128B rows, SW128), warp tile 64x32, m16n8k16
__global__ __launch_bounds__(256, 1)
void k_tgemm() {
    extern __shared__ char smem[];
    uint32_t sb = s2u(smem);
    int tid = threadIdx.x;
    int lane = tid & 31, wid = tid >> 5;
    int wm = wid >> 2, wn = wid & 3;
    int row_l = lane >> 2, kq = lane & 3;
    unsigned axorm = (unsigned)row_l << 4;

    int g0 = blockIdx.x * 128, b0 = blockIdx.y * 128, ks = blockIdx.z;
    int cbase = ks * NCH_;
    const char* pbase = (const char*)(d_Ph + (size_t)b0 * KE_);
    const char* wbase = (const char*)(d_w2h + (size_t)g0 * KE_);

    auto fill = [&](int cl, int s) {
        int c = cbase + cl;
        uint32_t asm_ = sb + s * STAGE_B;
        uint32_t bsm = asm_ + 16384;
        const char* psrc = pbase + (size_t)c * 128;
        const char* wsrc = wbase + (size_t)c * 128;
#pragma unroll
        for (int p = 0; p < 4; ++p) {
            int i = tid + p * 256;
            int row = i >> 3;
            int cb = (i & 7) << 4;
            uint32_t sw = SWZ(row * 128 + cb);
            cp16(asm_ + sw, psrc + (size_t)row * (KE_ * 2) + cb);
            cp16(bsm + sw, wsrc + (size_t)row * (KE_ * 2) + cb);
        }
    };

    float acc[4][4][4];
#pragma unroll
    for (int mt = 0; mt < 4; ++mt)
#pragma unroll
        for (int nt = 0; nt < 4; ++nt)
#pragma unroll
            for (int q = 0; q < 4; ++q) acc[mt][nt][q] = 0.f;

#pragma unroll
    for (int cl = 0; cl < GSTAGES - 1; ++cl) {
        fill(cl, cl);
        asm volatile("cp.async.commit_group;" ::: "memory");
    }

    for (int it = 0; it < NCH_; ++it) {
        asm volatile("cp.async.wait_group %0;" :: "n"(GSTAGES - 2) : "memory");
        __syncthreads();

        int cf = it + GSTAGES - 1;
        if (cf < NCH_) fill(cf, cf % GSTAGES);
        asm volatile("cp.async.commit_group;" ::: "memory");

        const char* As = smem + (it % GSTAGES) * STAGE_B;
        const char* Bs = As + 16384;

#pragma unroll
        for (int kst = 0; kst < 4; ++kst) {
            uint32_t af[4][4];
#pragma unroll
            for (int mt = 0; mt < 4; ++mt) {
                unsigned m = wm * 64 + mt * 16 + row_l;
                unsigned base = m * 128 + kst * 32 + kq * 4;
                af[mt][0] = *(const uint32_t*)(As + (base ^ axorm));
                af[mt][1] = *(const uint32_t*)(As + ((base + 8 * 128) ^ axorm));
                af[mt][2] = *(const uint32_t*)(As + ((base + 16) ^ axorm));
                af[mt][3] = *(const uint32_t*)(As + ((base + 8 * 128 + 16) ^ axorm));
            }
            uint32_t bf[4][2];
#pragma unroll
            for (int nt = 0; nt < 4; ++nt) {
                unsigned n = wn * 32 + nt * 8 + row_l;
                unsigned base = n * 128 + kst * 32 + kq * 4;
                bf[nt][0] = *(const uint32_t*)(Bs + (base ^ axorm));
                bf[nt][1] = *(const uint32_t*)(Bs + ((base + 16) ^ axorm));
            }
#pragma unroll
            for (int mt = 0; mt < 4; ++mt)
#pragma unroll
                for (int nt = 0; nt < 4; ++nt)
                    mma_f16(acc[mt][nt], af[mt], bf[nt]);
        }
    }

#pragma unroll
    for (int mt = 0; mt < 4; ++mt) {
#pragma unroll
        for (int nt = 0; nt < 4; ++nt) {
            int grow = b0 + wm * 64 + mt * 16 + row_l;
            int gcol = g0 + wn * 32 + nt * 8 + kq * 2;
            *(float2*)&d_c2[ks][grow][gcol]     = make_float2(acc[mt][nt][0], acc[mt][nt][1]);
            *(float2*)&d_c2[ks][grow + 8][gcol] = make_float2(acc[mt][nt][2], acc[mt][nt][3]);
        }
    }
}

// ---------------- final loss ----------------
__global__ void k_loss(const float* __restrict__ images, float* __restrict__ out) {
    int b = blockIdx.x, t = threadIdx.x;
    float s = 0.f;
    for (int g = t; g < 512; g += 128) {
        float v = d_c2[0][b][g] + d_c2[1][b][g] + d_c2[2][b][g] + d_c2[3][b][g]
                - images[b * 512 + g];
        s += v * v;
    }
    __shared__ float red[128];
    red[t] = s; __syncthreads();
    for (int q = 64; q; q >>= 1) { if (t < q) red[t] += red[t + q]; __syncthreads(); }
    if (t == 0) out[b] = red[0] * (1.f / 512.f);
}

// ---------------- launch ----------------
extern "C" void kernel_launch(void* const* d_in, const int* in_sizes, int n_in,
                              void* d_out, int out_size) {
    const float* images = (const float*)d_in[0];
    const float* wimg   = (const float*)d_in[1];
    const float* wrec   = (const float*)d_in[2];
    const float* wrec2  = (const float*)d_in[3];
    const float* wimg2  = (const float*)d_in[4];
    float* out = (float*)d_out;

    cudaFuncSetAttribute(k_encode1,  cudaFuncAttributeMaxDynamicSharedMemorySize, SMEM_E1);
    cudaFuncSetAttribute(k_encode2b, cudaFuncAttributeMaxDynamicSharedMemorySize, SMEM_E2);
    cudaFuncSetAttribute(k_tgemm,    cudaFuncAttributeMaxDynamicSharedMemorySize, SMEM_G);

    k_prep1<<<dim3(65, 8), 256>>>(wimg, wimg2);
    k_qred<<<65, 256>>>();
    k_norms<<<1, 256>>>(wrec, wrec2);
    k_encode1<<<128, 256, SMEM_E1>>>(images, wimg, wrec);
    k_dot2<<<B_, 256>>>(images);
    k_encode2b<<<128, 256, SMEM_E2>>>(wrec2);
    k_buildP<<<B_, 256>>>();
    k_tgemm<<<dim3(4, 8, NSPLIT_), 256, SMEM_G>>>();
    k_loss<<<B_, 128>>>(images, out);
}

// round 6
// speedup vs baseline: 4.8152x; 1.1696x over previous
#include <cuda_runtime.h>
#include <cuda_fp16.h>
#include <cstdint>

#define B_   1024
#define G_   512
#define K_   128
#define J_   129
#define KJ_  16512
#define KE_  16640
#define NSPLIT_ 4
#define NCH_ 65
#define GSTAGES 3
#define STAGE_B 32768
#define SMEM_G (GSTAGES * STAGE_B)

// ---------------- device scratch ----------------
__device__ float d_wrecnorm[K_];
__device__ float d_wrec2norm[J_];
__device__ float d_wnorm1[K_];
__device__ float d_q[KJ_];
__device__ float d_corr[KJ_];
__device__ float d_qp[8][KJ_];
__device__ float d_cp[8][KJ_];
__device__ float d_wnp[8][K_];
__device__ float d_lg1[B_ * K_];
__device__ float d_xpd[B_ * K_];
__device__ int   d_idx[B_];
__device__ float d_xp2d[B_ * J_];
__device__ float d_dot2[B_ * J_];
__device__ __half d_Ph[(size_t)B_ * KE_];
__device__ __half d_w2h[(size_t)G_ * KE_];
__device__ float d_c2[NSPLIT_][B_][G_];

// ---------------- helpers ----------------
__device__ __forceinline__ uint32_t s2u(const void* p) {
    uint32_t r;
    asm("{ .reg .u64 t; cvta.to.shared.u64 t, %1; cvt.u32.u64 %0, t; }" : "=r"(r) : "l"(p));
    return r;
}
__device__ __forceinline__ void cp16(uint32_t dst, const void* src) {
    asm volatile("cp.async.cg.shared.global [%0], [%1], 16;" :: "r"(dst), "l"(src) : "memory");
}
#define SWZ(o) ((o) ^ ((((unsigned)(o)) >> 3) & 0x70u))

__device__ __forceinline__ void mma_f16(float* c, const uint32_t* a, const uint32_t* b) {
    asm volatile(
        "mma.sync.aligned.m16n8k16.row.col.f32.f16.f16.f32 "
        "{%0,%1,%2,%3}, {%4,%5,%6,%7}, {%8,%9}, {%0,%1,%2,%3};"
        : "+f"(c[0]), "+f"(c[1]), "+f"(c[2]), "+f"(c[3])
        : "r"(a[0]), "r"(a[1]), "r"(a[2]), "r"(a[3]), "r"(b[0]), "r"(b[1]));
}
__device__ __forceinline__ unsigned div129(unsigned kj) { return (kj * 32515u) >> 22; }
__device__ __forceinline__ float wmax(float v) {
#pragma unroll
    for (int o = 16; o; o >>= 1) v = fmaxf(v, __shfl_xor_sync(~0u, v, o));
    return v;
}
__device__ __forceinline__ float wsum(float v) {
#pragma unroll
    for (int o = 16; o; o >>= 1) v += __shfl_xor_sync(~0u, v, o);
    return v;
}

// ---------------- wimg2 pass ----------------
__global__ void k_prep1(const float* __restrict__ wimg,
                        const float* __restrict__ wimg2) {
    int t = blockIdx.x * 256 + threadIdx.x;
    int gh = blockIdx.y;
    int gbeg = gh * 64;
    if (t < KJ_) {
        unsigned k = div129((unsigned)t);
        float q = 0.f, c = 0.f;
        for (int gg = 0; gg < 64; ++gg) {
            int g = gbeg + gg;
            float v = wimg2[(size_t)g * KJ_ + t];
            float wi = wimg[g * K_ + k];
            q += v * v;
            c += wi * v;
            d_w2h[(size_t)g * KE_ + t] = __float2half(v);
        }
        d_qp[gh][t] = q;
        d_cp[gh][t] = c;
    } else if (t < KE_) {
        int kk = t - KJ_;
        float s = 0.f;
        for (int gg = 0; gg < 64; ++gg) {
            int g = gbeg + gg;
            float v = wimg[g * K_ + kk];
            s += v * v;
            d_w2h[(size_t)g * KE_ + t] = __float2half(v);
        }
        d_wnp[gh][kk] = s;
    }
}

__global__ void k_qred() {
    int t = blockIdx.x * 256 + threadIdx.x;
    if (t < KJ_) {
        float q = 0.f, c = 0.f;
#pragma unroll
        for (int h = 0; h < 8; ++h) { q += d_qp[h][t]; c += d_cp[h][t]; }
        d_q[t] = q;
        d_corr[t] = c;
    } else if (t < KE_) {
        int kk = t - KJ_;
        float s = 0.f;
#pragma unroll
        for (int h = 0; h < 8; ++h) s += d_wnp[h][kk];
        d_wnorm1[kk] = s;
    }
}

__global__ void k_norms(const float* __restrict__ wrec,
                        const float* __restrict__ wrec2) {
    int t = threadIdx.x;
    if (t < K_) {
        float s = 0.f; const float* r = wrec + t * 128;
        for (int e = 0; e < 128; ++e) s += r[e] * r[e];
        d_wrecnorm[t] = s;
    }
    if (t < J_) {
        float s = 0.f; const float* r = wrec2 + t * 128;
        for (int e = 0; e < 128; ++e) s += r[e] * r[e];
        d_wrec2norm[t] = s;
    }
}

// ---------------- logits1 GEMM: grid 128, block 256, 8 b's per CTA ----------------
__global__ void k_log1(const float* __restrict__ images,
                       const float* __restrict__ wimg) {
    __shared__ float img_s[8 * 512];
    __shared__ float dotp[2][8][128];
    int t = threadIdx.x;
    int b0 = blockIdx.x * 8;
    for (int i = t; i < 4096; i += 256)
        img_s[i] = images[b0 * 512 + i];
    __syncthreads();

    int k = t & 127, gh = t >> 7;
    float a8[8];
#pragma unroll
    for (int bi = 0; bi < 8; ++bi) a8[bi] = 0.f;
#pragma unroll 4
    for (int gg = 0; gg < 256; ++gg) {
        int g = gh * 256 + gg;
        float w = wimg[g * 128 + k];
#pragma unroll
        for (int bi = 0; bi < 8; ++bi) a8[bi] += w * img_s[bi * 512 + g];
    }
#pragma unroll
    for (int bi = 0; bi < 8; ++bi) dotp[gh][bi][k] = a8[bi];
    __syncthreads();

    for (int i = t; i < 1024; i += 256) {
        int bi = i >> 7, kk = i & 127;
        float dot = dotp[0][bi][kk] + dotp[1][bi][kk];
        d_lg1[(b0 + bi) * 128 + kk] = (2.f * dot - d_wnorm1[kk]) * (1.f / 512.f);
    }
}

// ---------------- softmax1 -> lat -> logits2 -> softmax2+argmax ----------------
// grid 128, block 256 (8 warps, one b per warp for the warp-level phases)
#define SMEM_L2 ((16512 + 1024 + 1024 + 1024) * 4)
__global__ void k_latlog2(const float* __restrict__ wrec) {
    extern __shared__ float sm[];
    float* wrec_s = sm;              // [k*129+e], 16512
    float* xp1_s  = wrec_s + 16512;  // [8][128]
    float* lat_s  = xp1_s + 1024;    // [8][128]
    float* lg2_s  = lat_s + 1024;    // [8][128]

    int t = threadIdx.x, lane = t & 31, w = t >> 5;
    int b0 = blockIdx.x * 8;
    int b = b0 + w;

    for (int i = t; i < 16384; i += 256)
        wrec_s[(i >> 7) * 129 + (i & 127)] = wrec[i];

    // warp softmax of lg1 (k = q*32+lane)
    {
        float v[4];
#pragma unroll
        for (int q = 0; q < 4; ++q) v[q] = d_lg1[b * 128 + q * 32 + lane];
        float m = fmaxf(fmaxf(v[0], v[1]), fmaxf(v[2], v[3]));
        m = wmax(m);
        float e0 = __expf(v[0] - m), e1 = __expf(v[1] - m);
        float e2 = __expf(v[2] - m), e3 = __expf(v[3] - m);
        float s = wsum(e0 + e1 + e2 + e3);
        float inv = 1.f / s;
        xp1_s[w * 128 + lane]      = e0 * inv;
        xp1_s[w * 128 + 32 + lane] = e1 * inv;
        xp1_s[w * 128 + 64 + lane] = e2 * inv;
        xp1_s[w * 128 + 96 + lane] = e3 * inv;
    }
    __syncthreads();

    // lat[bi][e] = sum_k xp1[bi][k] * wrec[k][e]
    for (int i = t; i < 1024; i += 256) {
        int bi = i >> 7, e = i & 127;
        float acc = 0.f;
        const float* xp = xp1_s + bi * 128;
#pragma unroll 4
        for (int k = 0; k < 128; ++k) acc += xp[k] * wrec_s[k * 129 + e];
        lat_s[i] = acc;
    }
    __syncthreads();

    // lg2[bi][tt] = (2 * lat[bi].wrec[tt] - norm[tt]) / 128
    for (int i = t; i < 1024; i += 256) {
        int bi = i >> 7, tt = i & 127;
        float acc = 0.f;
        const float* lt = lat_s + bi * 128;
#pragma unroll 4
        for (int e = 0; e < 128; ++e) acc += lt[e] * wrec_s[tt * 129 + e];
        lg2_s[i] = (2.f * acc - d_wrecnorm[tt]) * (1.f / 128.f);
    }
    __syncthreads();

    // warp softmax + argmax of lg2
    {
        float v[4];
#pragma unroll
        for (int q = 0; q < 4; ++q) v[q] = lg2_s[w * 128 + q * 32 + lane];
        float bv = v[0]; int bk = lane;
#pragma unroll
        for (int q = 1; q < 4; ++q)
            if (v[q] > bv) { bv = v[q]; bk = q * 32 + lane; }
#pragma unroll
        for (int o = 16; o; o >>= 1) {
            float ov = __shfl_xor_sync(~0u, bv, o);
            int   ok = __shfl_xor_sync(~0u, bk, o);
            if (ov > bv || (ov == bv && ok < bk)) { bv = ov; bk = ok; }
        }
        if (lane == 0) d_idx[b] = bk;
        float m = bv;   // max value
        float e0 = __expf(v[0] - m), e1 = __expf(v[1] - m);
        float e2 = __expf(v[2] - m), e3 = __expf(v[3] - m);
        float s = wsum(e0 + e1 + e2 + e3);
        float inv = 1.f / s;
        d_xpd[b * 128 + lane]      = e0 * inv;
        d_xpd[b * 128 + 32 + lane] = e1 * inv;
        d_xpd[b * 128 + 64 + lane] = e2 * inv;
        d_xpd[b * 128 + 96 + lane] = e3 * inv;
    }
}

// ---------------- dot2 ----------------
__global__ void k_dot2(const float* __restrict__ images) {
    __shared__ float img_s[512];
    __shared__ float part[8][136];
    int b = blockIdx.x, t = threadIdx.x, lane = t & 31, w = t >> 5;
    for (int i = t; i < 512; i += 256) img_s[i] = images[b * 512 + i];
    __syncthreads();
    int idx = d_idx[b];
    const __half* colb = d_w2h + (size_t)idx * 129;
    float a0 = 0.f, a1 = 0.f, a2 = 0.f, a3 = 0.f, a4 = 0.f;
    for (int g = w; g < 512; g += 8) {
        float iv = img_s[g];
        const __half* rp = colb + (size_t)g * KE_;
        a0 += iv * __half2float(rp[lane]);
        a1 += iv * __half2float(rp[lane + 32]);
        a2 += iv * __half2float(rp[lane + 64]);
        a3 += iv * __half2float(rp[lane + 96]);
        if (lane == 0) a4 += iv * __half2float(rp[128]);
    }
    part[w][lane] = a0; part[w][lane + 32] = a1;
    part[w][lane + 64] = a2; part[w][lane + 96] = a3;
    if (lane == 0) part[w][128] = a4;
    __syncthreads();
    if (t < 129) {
        float s = 0.f;
#pragma unroll
        for (int ww = 0; ww < 8; ++ww) s += part[ww][t];
        d_dot2[b * J_ + t] = s;
    }
}

// ---------------- softmax3 -> lat2 -> logits4 -> softmax4 ----------------
// grid 128, block 256
#define SMEM_L4 ((16641 + 1056 + 1024 + 1056) * 4)
__global__ void k_latlog4(const float* __restrict__ wrec2) {
    extern __shared__ float sm[];
    float* wrec2_s = sm;               // [j*129+e], j<129 -> 16641
    float* xp2_s   = wrec2_s + 16641;  // [8][132]
    float* lat2_s  = xp2_s + 1056;     // [8][128]
    float* lg4_s   = lat2_s + 1024;    // [8][132]

    int t = threadIdx.x, lane = t & 31, w = t >> 5;
    int b0 = blockIdx.x * 8;
    int b = b0 + w;
    int idx = d_idx[b];

    for (int i = t; i < 16512; i += 256)
        wrec2_s[(i >> 7) * 129 + (i & 127)] = wrec2[i];

    // warp softmax over 129 logits3 (lane0 carries j=128 extra)
    {
        const float* dt = d_dot2 + b * J_;
        const float* cr = d_corr + idx * J_;
        const float* qq = d_q + idx * J_;
        float v[4], v4;
#pragma unroll
        for (int q = 0; q < 4; ++q) {
            int j = q * 32 + lane;
            v[q] = (2.f * (dt[j] - cr[j]) - qq[j]) * (1.f / 512.f);
        }
        v4 = (lane == 0) ? (2.f * (dt[128] - cr[128]) - qq[128]) * (1.f / 512.f) : -INFINITY;
        float m = fmaxf(fmaxf(fmaxf(v[0], v[1]), fmaxf(v[2], v[3])), v4);
        m = wmax(m);
        float e0 = __expf(v[0] - m), e1 = __expf(v[1] - m);
        float e2 = __expf(v[2] - m), e3 = __expf(v[3] - m);
        float e4 = (lane == 0) ? __expf(v4 - m) : 0.f;
        float s = wsum(e0 + e1 + e2 + e3 + e4);
        float inv = 1.f / s;
        xp2_s[w * 132 + lane]      = e0 * inv;
        xp2_s[w * 132 + 32 + lane] = e1 * inv;
        xp2_s[w * 132 + 64 + lane] = e2 * inv;
        xp2_s[w * 132 + 96 + lane] = e3 * inv;
        if (lane == 0) xp2_s[w * 132 + 128] = e4 * inv;
    }
    __syncthreads();

    // lat2[bi][e] = sum_{j<129} xp2[bi][j] * wrec2[j][e]
    for (int i = t; i < 1024; i += 256) {
        int bi = i >> 7, e = i & 127;
        float acc = 0.f;
        const float* xp = xp2_s + bi * 132;
#pragma unroll 4
        for (int j = 0; j < 129; ++j) acc += xp[j] * wrec2_s[j * 129 + e];
        lat2_s[i] = acc;
    }
    __syncthreads();

    // lg4[bi][tt] for tt<129
    for (int i = t; i < 1032; i += 256) {
        unsigned bi = div129((unsigned)i);
        unsigned tt = (unsigned)i - bi * 129u;
        float acc = 0.f;
        const float* lt = lat2_s + bi * 128;
#pragma unroll 4
        for (int e = 0; e < 128; ++e) acc += lt[e] * wrec2_s[tt * 129 + e];
        lg4_s[bi * 132 + tt] = (2.f * acc - d_wrec2norm[tt]) * (1.f / 128.f);
    }
    __syncthreads();

    // warp softmax over 129 -> d_xp2d
    {
        float v[4];
#pragma unroll
        for (int q = 0; q < 4; ++q) v[q] = lg4_s[w * 132 + q * 32 + lane];
        float v4 = (lane == 0) ? lg4_s[w * 132 + 128] : -INFINITY;
        float m = fmaxf(fmaxf(fmaxf(v[0], v[1]), fmaxf(v[2], v[3])), v4);
        m = wmax(m);
        float e0 = __expf(v[0] - m), e1 = __expf(v[1] - m);
        float e2 = __expf(v[2] - m), e3 = __expf(v[3] - m);
        float e4 = (lane == 0) ? __expf(v4 - m) : 0.f;
        float s = wsum(e0 + e1 + e2 + e3 + e4);
        float inv = 1.f / s;
        d_xp2d[b * J_ + lane]      = e0 * inv;
        d_xp2d[b * J_ + 32 + lane] = e1 * inv;
        d_xp2d[b * J_ + 64 + lane] = e2 * inv;
        d_xp2d[b * J_ + 96 + lane] = e3 * inv;
        if (lane == 0) d_xp2d[b * J_ + 128] = e4 * inv;
    }
}

// ---------------- build P (f16) ----------------
__global__ void k_buildP() {
    __shared__ float xp_s[128];
    __shared__ float xp2_s[132];
    int b = blockIdx.x, t = threadIdx.x;
    if (t < 128) xp_s[t] = d_xpd[b * 128 + t];
    if (t < 129) xp2_s[t] = d_xp2d[b * J_ + t];
    __syncthreads();
    __half2* dst = (__half2*)(d_Ph + (size_t)b * KE_);
    for (int i2 = t; i2 < KE_ / 2; i2 += 256) {
        int kj = i2 * 2;
        float v0, v1;
        if (kj < KJ_) {
            unsigned k = div129((unsigned)kj);
            unsigned j = (unsigned)kj - k * 129u;
            float xk = xp_s[k];
            v0 = xk * xp2_s[j];
            v1 = (j < 128) ? xk * xp2_s[j + 1] : xp_s[k + 1] * xp2_s[0];
        } else {
            v0 = xp_s[kj - KJ_];
            v1 = xp_s[kj - KJ_ + 1];
        }
        dst[i2] = __floats2half2_rn(v0, v1);
    }
}

// ---------------- f16 mma.sync GEMM ----------------
__global__ __launch_bounds__(256, 1)
void k_tgemm() {
    extern __shared__ char smem[];
    uint32_t sb = s2u(smem);
    int tid = threadIdx.x;
    int lane = tid & 31, wid = tid >> 5;
    int wm = wid >> 2, wn = wid & 3;
    int row_l = lane >> 2, kq = lane & 3;
    unsigned axorm = (unsigned)row_l << 4;

    int g0 = blockIdx.x * 128, b0 = blockIdx.y * 128, ks = blockIdx.z;
    int cbase = ks * NCH_;
    const char* pbase = (const char*)(d_Ph + (size_t)b0 * KE_);
    const char* wbase = (const char*)(d_w2h + (size_t)g0 * KE_);

    auto fill = [&](int cl, int s) {
        int c = cbase + cl;
        uint32_t asm_ = sb + s * STAGE_B;
        uint32_t bsm = asm_ + 16384;
        const char* psrc = pbase + (size_t)c * 128;
        const char* wsrc = wbase + (size_t)c * 128;
#pragma unroll
        for (int p = 0; p < 4; ++p) {
            int i = tid + p * 256;
            int row = i >> 3;
            int cb = (i & 7) << 4;
            uint32_t sw = SWZ(row * 128 + cb);
            cp16(asm_ + sw, psrc + (size_t)row * (KE_ * 2) + cb);
            cp16(bsm + sw, wsrc + (size_t)row * (KE_ * 2) + cb);
        }
    };

    float acc[4][4][4];
#pragma unroll
    for (int mt = 0; mt < 4; ++mt)
#pragma unroll
        for (int nt = 0; nt < 4; ++nt)
#pragma unroll
            for (int q = 0; q < 4; ++q) acc[mt][nt][q] = 0.f;

#pragma unroll
    for (int cl = 0; cl < GSTAGES - 1; ++cl) {
        fill(cl, cl);
        asm volatile("cp.async.commit_group;" ::: "memory");
    }

    for (int it = 0; it < NCH_; ++it) {
        asm volatile("cp.async.wait_group %0;" :: "n"(GSTAGES - 2) : "memory");
        __syncthreads();

        int cf = it + GSTAGES - 1;
        if (cf < NCH_) fill(cf, cf % GSTAGES);
        asm volatile("cp.async.commit_group;" ::: "memory");

        const char* As = smem + (it % GSTAGES) * STAGE_B;
        const char* Bs = As + 16384;

#pragma unroll
        for (int kst = 0; kst < 4; ++kst) {
            uint32_t af[4][4];
#pragma unroll
            for (int mt = 0; mt < 4; ++mt) {
                unsigned m = wm * 64 + mt * 16 + row_l;
                unsigned base = m * 128 + kst * 32 + kq * 4;
                af[mt][0] = *(const uint32_t*)(As + (base ^ axorm));
                af[mt][1] = *(const uint32_t*)(As + ((base + 8 * 128) ^ axorm));
                af[mt][2] = *(const uint32_t*)(As + ((base + 16) ^ axorm));
                af[mt][3] = *(const uint32_t*)(As + ((base + 8 * 128 + 16) ^ axorm));
            }
            uint32_t bf[4][2];
#pragma unroll
            for (int nt = 0; nt < 4; ++nt) {
                unsigned n = wn * 32 + nt * 8 + row_l;
                unsigned base = n * 128 + kst * 32 + kq * 4;
                bf[nt][0] = *(const uint32_t*)(Bs + (base ^ axorm));
                bf[nt][1] = *(const uint32_t*)(Bs + ((base + 16) ^ axorm));
            }
#pragma unroll
            for (int mt = 0; mt < 4; ++mt)
#pragma unroll
                for (int nt = 0; nt < 4; ++nt)
                    mma_f16(acc[mt][nt], af[mt], bf[nt]);
        }
    }

#pragma unroll
    for (int mt = 0; mt < 4; ++mt) {
#pragma unroll
        for (int nt = 0; nt < 4; ++nt) {
            int grow = b0 + wm * 64 + mt * 16 + row_l;
            int gcol = g0 + wn * 32 + nt * 8 + kq * 2;
            *(float2*)&d_c2[ks][grow][gcol]     = make_float2(acc[mt][nt][0], acc[mt][nt][1]);
            *(float2*)&d_c2[ks][grow + 8][gcol] = make_float2(acc[mt][nt][2], acc[mt][nt][3]);
        }
    }
}

// ---------------- final loss ----------------
__global__ void k_loss(const float* __restrict__ images, float* __restrict__ out) {
    int b = blockIdx.x, t = threadIdx.x;
    float s = 0.f;
    for (int g = t; g < 512; g += 128) {
        float v = d_c2[0][b][g] + d_c2[1][b][g] + d_c2[2][b][g] + d_c2[3][b][g]
                - images[b * 512 + g];
        s += v * v;
    }
    __shared__ float red[128];
    red[t] = s; __syncthreads();
    for (int q = 64; q; q >>= 1) { if (t < q) red[t] += red[t + q]; __syncthreads(); }
    if (t == 0) out[b] = red[0] * (1.f / 512.f);
}

// ---------------- launch ----------------
extern "C" void kernel_launch(void* const* d_in, const int* in_sizes, int n_in,
                              void* d_out, int out_size) {
    const float* images = (const float*)d_in[0];
    const float* wimg   = (const float*)d_in[1];
    const float* wrec   = (const float*)d_in[2];
    const float* wrec2  = (const float*)d_in[3];
    const float* wimg2  = (const float*)d_in[4];
    float* out = (float*)d_out;

    cudaFuncSetAttribute(k_latlog2, cudaFuncAttributeMaxDynamicSharedMemorySize, SMEM_L2);
    cudaFuncSetAttribute(k_latlog4, cudaFuncAttributeMaxDynamicSharedMemorySize, SMEM_L4);
    cudaFuncSetAttribute(k_tgemm,   cudaFuncAttributeMaxDynamicSharedMemorySize, SMEM_G);

    k_prep1<<<dim3(65, 8), 256>>>(wimg, wimg2);
    k_qred<<<65, 256>>>();
    k_norms<<<1, 256>>>(wrec, wrec2);
    k_log1<<<128, 256>>>(images, wimg);
    k_latlog2<<<128, 256, SMEM_L2>>>(wrec);
    k_dot2<<<B_, 256>>>(images);
    k_latlog4<<<128, 256, SMEM_L4>>>(wrec2);
    k_buildP<<<B_, 256>>>();
    k_tgemm<<<dim3(4, 8, NSPLIT_), 256, SMEM_G>>>();
    k_loss<<<B_, 128>>>(images, out);
}